// round 8
// baseline (speedup 1.0000x reference)
#include <cuda_runtime.h>
#include <cuda_fp16.h>

#define DD   64
#define MAXN 100000
#define MAXE 1600000
#define NREL 201

// Scratch (allocation-free rule: __device__ globals)
// g_EP: per node 128 halves, interleaved per 4-dim lane: [expG x4 | P x4]
__device__ __half    g_EP[MAXN * 128];
__device__ float     g_expEgb[NREL * DD];   // exp(E_gate + B_gate_pre)
__device__ int       g_cnt[MAXN];
__device__ int       g_incl[MAXN];
__device__ int       g_btot[128];
__device__ int       g_start[MAXN];
__device__ int       g_rank[MAXE];          // within-receiver rank of each edge
__device__ unsigned  g_edge[MAXE];          // sender | (type<<17), grouped by receiver

// ---------------------------------------------------------------------------
// tf32 helpers
// ---------------------------------------------------------------------------
__device__ __forceinline__ unsigned f2tf32(float x) {
    unsigned r;
    asm("cvt.rna.tf32.f32 %0, %1;" : "=r"(r) : "f"(x));
    return r;
}

#define MMA_TF32(d0,d1,d2,d3,a0,a1,a2,a3,b0,b1) \
    asm volatile("mma.sync.aligned.m16n8k8.row.col.f32.tf32.tf32.f32 " \
        "{%0,%1,%2,%3}, {%4,%5,%6,%7}, {%8,%9}, {%0,%1,%2,%3};" \
        : "+f"(d0), "+f"(d1), "+f"(d2), "+f"(d3) \
        : "r"(a0), "r"(a1), "r"(a2), "r"(a3), "r"(b0), "r"(b1))

// ---------------------------------------------------------------------------
// Fused front kernel. Block roles by blockIdx.x:
//   [0, nodeBlocks)              : tensor-core node GEMMs -> g_EP
//   [nodeBlocks, nodeBlocks+eb)  : expEgb = exp(E_gate + B_gate_pre)
//   [nodeBlocks+eb, ...)         : histogram (rank via atomic), 4 edges/thread
// ---------------------------------------------------------------------------
__global__ void __launch_bounds__(256) fused_front_kernel(
    const float* __restrict__ X,
    const float* __restrict__ Vp,
    const float* __restrict__ Vg,
    const float* __restrict__ Bm,
    const float* __restrict__ Eg,
    const float* __restrict__ Bg,
    const int*   __restrict__ rcv,
    int N, int E, int nodeBlocks, int egbBlocks)
{
    extern __shared__ unsigned sB[];   // node role: 2*8*8*2*32 uint2 = 64KB
    const int tid = threadIdx.x;
    const int bid = blockIdx.x;

    if (bid >= nodeBlocks) {
        if (bid < nodeBlocks + egbBlocks) {
            const int i = (bid - nodeBlocks) * 256 + tid;
            if (i < NREL * DD) g_expEgb[i] = __expf(Eg[i] + Bg[i & (DD - 1)]);
        } else {
            const int chunk = (bid - nodeBlocks - egbBlocks) * 1024;
            #pragma unroll
            for (int j = 0; j < 4; j++) {
                const int e = chunk + j * 256 + tid;
                if (e < E) g_rank[e] = atomicAdd(&g_cnt[rcv[e]], 1);
            }
        }
        return;
    }

    // ---- node role ----
    for (int idx = tid; idx < 2 * 8 * 8 * 2 * 32; idx += 256) {
        const int lane = idx & 31;
        const int hl   = (idx >> 5) & 1;
        const int k    = (idx >> 6) & 7;
        const int n    = (idx >> 9) & 7;
        const int mat  = (idx >> 12) & 1;
        const float* __restrict__ V = (mat == 0) ? Vg : Vp;
        const int t = lane & 3, g = lane >> 2;
        const float v0 = V[(k * 8 + t) * DD + n * 8 + g];
        const float v1 = V[(k * 8 + t + 4) * DD + n * 8 + g];
        unsigned o0, o1;
        if (hl == 0) {
            o0 = f2tf32(v0);
            o1 = f2tf32(v1);
        } else {
            const unsigned h0 = f2tf32(v0), h1 = f2tf32(v1);
            o0 = f2tf32(v0 - __uint_as_float(h0));
            o1 = f2tf32(v1 - __uint_as_float(h1));
        }
        ((uint2*)sB)[idx] = make_uint2(o0, o1);
    }
    __syncthreads();

    const int warp = tid >> 5;
    const int lane = tid & 31;
    const int m0   = (bid * 8 + warp) * 16;
    if (m0 >= N) return;

    const int t = lane & 3, g = lane >> 2;
    const int r0 = m0 + g;
    const int r1 = m0 + g + 8;
    const bool r0ok = r0 < N;
    const bool r1ok = r1 < N;

    unsigned Ahi[8][4], Alo[8][4];
    const float* __restrict__ xr0 = X + (size_t)r0 * DD;
    const float* __restrict__ xr1 = X + (size_t)r1 * DD;
    #pragma unroll
    for (int k = 0; k < 8; k++) {
        float x0 = r0ok ? __ldg(&xr0[k * 8 + t])     : 0.f;
        float x1 = r1ok ? __ldg(&xr1[k * 8 + t])     : 0.f;
        float x2 = r0ok ? __ldg(&xr0[k * 8 + t + 4]) : 0.f;
        float x3 = r1ok ? __ldg(&xr1[k * 8 + t + 4]) : 0.f;
        Ahi[k][0] = f2tf32(x0); Alo[k][0] = f2tf32(x0 - __uint_as_float(Ahi[k][0]));
        Ahi[k][1] = f2tf32(x1); Alo[k][1] = f2tf32(x1 - __uint_as_float(Ahi[k][1]));
        Ahi[k][2] = f2tf32(x2); Alo[k][2] = f2tf32(x2 - __uint_as_float(Ahi[k][2]));
        Ahi[k][3] = f2tf32(x3); Alo[k][3] = f2tf32(x3 - __uint_as_float(Ahi[k][3]));
    }

    const uint2* __restrict__ sB2 = (const uint2*)sB;

    #pragma unroll
    for (int mat = 0; mat < 2; mat++) {
        #pragma unroll
        for (int n = 0; n < 8; n++) {
            float d0 = 0.f, d1 = 0.f, d2 = 0.f, d3 = 0.f;
            #pragma unroll
            for (int k = 0; k < 8; k++) {
                const int base = (((mat * 8 + n) * 8 + k) * 2) * 32 + lane;
                const uint2 bh = sB2[base];
                const uint2 bl = sB2[base + 32];
                MMA_TF32(d0, d1, d2, d3,
                         Ahi[k][0], Ahi[k][1], Ahi[k][2], Ahi[k][3], bh.x, bh.y);
                MMA_TF32(d0, d1, d2, d3,
                         Ahi[k][0], Ahi[k][1], Ahi[k][2], Ahi[k][3], bl.x, bl.y);
                MMA_TF32(d0, d1, d2, d3,
                         Alo[k][0], Alo[k][1], Alo[k][2], Alo[k][3], bh.x, bh.y);
            }
            const int c0 = n * 8 + 2 * t;      // even column
            const int li = c0 >> 2;
            const int offG = li * 8 + (c0 & 3);
            const int offP = li * 8 + 4 + (c0 & 3);
            if (mat == 0) {
                if (r0ok) *(__half2*)&g_EP[(size_t)r0 * 128 + offG] =
                    __floats2half2_rn(__expf(d0), __expf(d1));
                if (r1ok) *(__half2*)&g_EP[(size_t)r1 * 128 + offG] =
                    __floats2half2_rn(__expf(d2), __expf(d3));
            } else {
                const float b0v = __ldg(&Bm[c0]);
                const float b1v = __ldg(&Bm[c0 + 1]);
                if (r0ok) *(__half2*)&g_EP[(size_t)r0 * 128 + offP] =
                    __floats2half2_rn(fmaxf(d0 + b0v, 0.f), fmaxf(d1 + b1v, 0.f));
                if (r1ok) *(__half2*)&g_EP[(size_t)r1 * 128 + offP] =
                    __floats2half2_rn(fmaxf(d2 + b0v, 0.f), fmaxf(d3 + b1v, 0.f));
            }
        }
    }
}

// ---------------------------------------------------------------------------
// Scan, then scatter via saved ranks (no second atomic pass)
// ---------------------------------------------------------------------------
__global__ void __launch_bounds__(1024) scan1_kernel(int N)
{
    __shared__ int wsum[32];
    const int i    = blockIdx.x * 1024 + threadIdx.x;
    const int lane = threadIdx.x & 31;
    const int w    = threadIdx.x >> 5;

    int s = (i < N) ? g_cnt[i] : 0;
    #pragma unroll
    for (int d = 1; d < 32; d <<= 1) {
        int tv = __shfl_up_sync(0xffffffffu, s, d);
        if (lane >= d) s += tv;
    }
    if (lane == 31) wsum[w] = s;
    __syncthreads();
    if (w == 0) {
        int ws = wsum[lane];
        #pragma unroll
        for (int d = 1; d < 32; d <<= 1) {
            int tv = __shfl_up_sync(0xffffffffu, ws, d);
            if (lane >= d) ws += tv;
        }
        wsum[lane] = ws;
    }
    __syncthreads();
    if (w > 0) s += wsum[w - 1];
    if (i < N) g_incl[i] = s;
    if (threadIdx.x == 1023) g_btot[blockIdx.x] = s;
}

__global__ void __launch_bounds__(256) scan23_kernel(int N, int nblk)
{
    __shared__ int sm[128];
    if (threadIdx.x < 128)
        sm[threadIdx.x] = (threadIdx.x < nblk) ? g_btot[threadIdx.x] : 0;
    __syncthreads();
    #pragma unroll
    for (int d = 1; d < 128; d <<= 1) {
        int t = 0;
        if (threadIdx.x < 128 && threadIdx.x >= d) t = sm[threadIdx.x - d];
        __syncthreads();
        if (threadIdx.x < 128) sm[threadIdx.x] += t;
        __syncthreads();
    }
    const int i = blockIdx.x * blockDim.x + threadIdx.x;
    if (i < N) {
        const int blk = i >> 10;
        const int boff = (blk == 0) ? 0 : sm[blk - 1];
        g_start[i] = g_incl[i] - g_cnt[i] + boff;
    }
}

__global__ void __launch_bounds__(256) scatter_kernel(
    const int* __restrict__ snd, const int* __restrict__ rcv,
    const int* __restrict__ typ, int E)
{
    const int base = blockIdx.x * 1024;
    #pragma unroll
    for (int j = 0; j < 4; j++) {
        const int e = base + j * 256 + threadIdx.x;
        if (e < E) {
            const int pos = g_start[rcv[e]] + g_rank[e];
            g_edge[pos] = (unsigned)snd[e] | ((unsigned)typ[e] << 17);
        }
    }
}

// ---------------------------------------------------------------------------
// Consume: PERSISTENT warps, strided over receivers for load balance.
// Each warp handles receivers {w, w+W, w+2W, ...}; per receiver the two
// half-warps take contiguous halves of the edge range; 16 lanes cover D=64
// (4 dims/lane). One LDG.128 per edge per lane, fp32 accumulate, 4-edge
// unroll for MLP. No atomics, single output write per receiver.
// ---------------------------------------------------------------------------
__device__ __forceinline__ void edge_accum(
    unsigned e, int li, const uint4* __restrict__ EP4,
    const float4* __restrict__ Eg4, float4& num, float4& den)
{
    const int s = (int)(e & 0x1FFFFu);
    const int t = (int)(e >> 17);

    const uint4  v  = EP4[s * 16 + li];        // expG x4 | P x4 (fp16)
    const float4 eg = Eg4[t * 16 + li];        // exp(Eg+Bg), fp32 (hot)

    const float2 g01 = __half22float2(*(const __half2*)&v.x);
    const float2 g23 = __half22float2(*(const __half2*)&v.y);
    const float2 p01 = __half22float2(*(const __half2*)&v.z);
    const float2 p23 = __half22float2(*(const __half2*)&v.w);

    const float ex0 = g01.x * eg.x;
    const float ex1 = g01.y * eg.y;
    const float ex2 = g23.x * eg.z;
    const float ex3 = g23.y * eg.w;

    den.x += ex0; den.y += ex1; den.z += ex2; den.w += ex3;
    num.x += p01.x * ex0;
    num.y += p01.y * ex1;
    num.z += p23.x * ex2;
    num.w += p23.y * ex3;
}

__global__ void __launch_bounds__(256) consume_kernel(
    float4* __restrict__ out, int N, int W)
{
    const int warp0 = (blockIdx.x * blockDim.x + threadIdx.x) >> 5;
    const int lane  = threadIdx.x & 31;
    const int half  = lane >> 4;
    const int li    = lane & 15;

    const uint4*  EP4 = (const uint4*)g_EP;
    const float4* Eg4 = (const float4*)g_expEgb;

    for (int gw = warp0; gw < N; gw += W) {
        const int start = g_start[gw];
        const int cnt   = g_cnt[gw];
        const int mid   = start + ((cnt + 1) >> 1);
        const int lo    = half ? mid : start;
        const int hi    = half ? (start + cnt) : mid;

        float4 num = make_float4(0.f, 0.f, 0.f, 0.f);
        float4 den = make_float4(0.f, 0.f, 0.f, 0.f);

        int i = lo;
        for (; i + 3 < hi; i += 4) {
            const unsigned e0 = g_edge[i];
            const unsigned e1 = g_edge[i + 1];
            const unsigned e2 = g_edge[i + 2];
            const unsigned e3 = g_edge[i + 3];
            edge_accum(e0, li, EP4, Eg4, num, den);
            edge_accum(e1, li, EP4, Eg4, num, den);
            edge_accum(e2, li, EP4, Eg4, num, den);
            edge_accum(e3, li, EP4, Eg4, num, den);
        }
        for (; i < hi; i++) {
            edge_accum(g_edge[i], li, EP4, Eg4, num, den);
        }

        num.x += __shfl_xor_sync(0xffffffffu, num.x, 16);
        num.y += __shfl_xor_sync(0xffffffffu, num.y, 16);
        num.z += __shfl_xor_sync(0xffffffffu, num.z, 16);
        num.w += __shfl_xor_sync(0xffffffffu, num.w, 16);
        den.x += __shfl_xor_sync(0xffffffffu, den.x, 16);
        den.y += __shfl_xor_sync(0xffffffffu, den.y, 16);
        den.z += __shfl_xor_sync(0xffffffffu, den.z, 16);
        den.w += __shfl_xor_sync(0xffffffffu, den.w, 16);

        if (half == 0) {
            float4 v;
            v.x = (den.x > 0.f) ? num.x / den.x : 0.f;
            v.y = (den.y > 0.f) ? num.y / den.y : 0.f;
            v.z = (den.z > 0.f) ? num.z / den.z : 0.f;
            v.w = (den.w > 0.f) ? num.w / den.w : 0.f;
            out[gw * 16 + li] = v;
        }
    }
}

extern "C" void kernel_launch(void* const* d_in, const int* in_sizes, int n_in,
                              void* d_out, int out_size)
{
    const float* node_codes = (const float*)d_in[0];
    const float* Vp         = (const float*)d_in[1];
    const float* Vg         = (const float*)d_in[2];
    const float* Eg         = (const float*)d_in[3];
    const float* Bm         = (const float*)d_in[4];
    const float* Bg         = (const float*)d_in[5];
    const int*   snd        = (const int*)d_in[6];
    const int*   rcv        = (const int*)d_in[7];
    const int*   typ        = (const int*)d_in[8];

    const int N = in_sizes[0] / DD;
    const int E = in_sizes[6];

    const int SMEM_B = 2 * 8 * 8 * 2 * 32 * 8;   // 65536 bytes
    cudaFuncSetAttribute(fused_front_kernel,
                         cudaFuncAttributeMaxDynamicSharedMemorySize, SMEM_B);

    void* cntp = nullptr;
    cudaGetSymbolAddress(&cntp, g_cnt);
    cudaMemsetAsync(cntp, 0, (size_t)N * sizeof(int));

    {
        const int nodeBlocks = ((N + 15) / 16 + 7) / 8;
        const int egbBlocks  = (NREL * DD + 255) / 256;
        const int histBlocks = (E + 1023) / 1024;
        const int total = nodeBlocks + egbBlocks + histBlocks;
        fused_front_kernel<<<total, 256, SMEM_B>>>(
            node_codes, Vp, Vg, Bm, Eg, Bg, rcv, N, E, nodeBlocks, egbBlocks);
    }

    const int nblk = (N + 1023) / 1024;
    scan1_kernel<<<nblk, 1024>>>(N);
    scan23_kernel<<<(N + 255) / 256, 256>>>(N, nblk);

    scatter_kernel<<<(E + 1023) / 1024, 256>>>(snd, rcv, typ, E);

    {
        // Persistent strided warps: ~12 blocks/SM worth of warps.
        const int blocks = 1776;
        const int W = blocks * (256 / 32);
        consume_kernel<<<blocks, 256>>>((float4*)d_out, N, W);
    }
}

// round 9
// speedup vs baseline: 1.0034x; 1.0034x over previous
#include <cuda_runtime.h>
#include <cuda_fp16.h>

#define DD   64
#define MAXN 100000
#define MAXE 1600000
#define NREL 201

// Scratch (allocation-free rule: __device__ globals).
// INVARIANT: g_cnt is all-zero at kernel_launch entry. True at load (BSS),
// and consume_kernel restores it after use on every call.
__device__ __half    g_EP[MAXN * 128];      // per node: [expG x4 | P x4] per lane
__device__ float     g_expEgb[NREL * DD];   // exp(E_gate + B_gate_pre)
__device__ int       g_cnt[MAXN];
__device__ int       g_incl[MAXN];
__device__ int       g_btot[128];
__device__ int       g_start[MAXN];
__device__ int       g_rank[MAXE];          // within-receiver rank of each edge
__device__ unsigned  g_pay[MAXE];           // sender | (type<<17), edge order
__device__ unsigned  g_edge[MAXE];          // payload grouped by receiver

// ---------------------------------------------------------------------------
// tf32 helpers
// ---------------------------------------------------------------------------
__device__ __forceinline__ unsigned f2tf32(float x) {
    unsigned r;
    asm("cvt.rna.tf32.f32 %0, %1;" : "=r"(r) : "f"(x));
    return r;
}

#define MMA_TF32(d0,d1,d2,d3,a0,a1,a2,a3,b0,b1) \
    asm volatile("mma.sync.aligned.m16n8k8.row.col.f32.tf32.tf32.f32 " \
        "{%0,%1,%2,%3}, {%4,%5,%6,%7}, {%8,%9}, {%0,%1,%2,%3};" \
        : "+f"(d0), "+f"(d1), "+f"(d2), "+f"(d3) \
        : "r"(a0), "r"(a1), "r"(a2), "r"(a3), "r"(b0), "r"(b1))

// ---------------------------------------------------------------------------
// Fused front kernel. Block roles by blockIdx.x:
//   [0, nodeBlocks)              : tensor-core node GEMMs -> g_EP
//   [nodeBlocks, nodeBlocks+eb)  : expEgb = exp(E_gate + B_gate_pre)
//   [nodeBlocks+eb, ...)         : histogram (rank via atomic) + payload pack
// ---------------------------------------------------------------------------
__global__ void __launch_bounds__(256) fused_front_kernel(
    const float* __restrict__ X,
    const float* __restrict__ Vp,
    const float* __restrict__ Vg,
    const float* __restrict__ Bm,
    const float* __restrict__ Eg,
    const float* __restrict__ Bg,
    const int*   __restrict__ snd,
    const int*   __restrict__ rcv,
    const int*   __restrict__ typ,
    int N, int E, int nodeBlocks, int egbBlocks)
{
    extern __shared__ unsigned sB[];   // node role: 2*8*8*2*32 uint2 = 64KB
    const int tid = threadIdx.x;
    const int bid = blockIdx.x;

    if (bid >= nodeBlocks) {
        if (bid < nodeBlocks + egbBlocks) {
            const int i = (bid - nodeBlocks) * 256 + tid;
            if (i < NREL * DD) g_expEgb[i] = __expf(Eg[i] + Bg[i & (DD - 1)]);
        } else {
            const int chunk = (bid - nodeBlocks - egbBlocks) * 1024;
            #pragma unroll
            for (int j = 0; j < 4; j++) {
                const int e = chunk + j * 256 + tid;
                if (e < E) {
                    g_rank[e] = atomicAdd(&g_cnt[rcv[e]], 1);
                    g_pay[e]  = (unsigned)snd[e] | ((unsigned)typ[e] << 17);
                }
            }
        }
        return;
    }

    // ---- node role ----
    for (int idx = tid; idx < 2 * 8 * 8 * 2 * 32; idx += 256) {
        const int lane = idx & 31;
        const int hl   = (idx >> 5) & 1;
        const int k    = (idx >> 6) & 7;
        const int n    = (idx >> 9) & 7;
        const int mat  = (idx >> 12) & 1;
        const float* __restrict__ V = (mat == 0) ? Vg : Vp;
        const int t = lane & 3, g = lane >> 2;
        const float v0 = V[(k * 8 + t) * DD + n * 8 + g];
        const float v1 = V[(k * 8 + t + 4) * DD + n * 8 + g];
        unsigned o0, o1;
        if (hl == 0) {
            o0 = f2tf32(v0);
            o1 = f2tf32(v1);
        } else {
            const unsigned h0 = f2tf32(v0), h1 = f2tf32(v1);
            o0 = f2tf32(v0 - __uint_as_float(h0));
            o1 = f2tf32(v1 - __uint_as_float(h1));
        }
        ((uint2*)sB)[idx] = make_uint2(o0, o1);
    }
    __syncthreads();

    const int warp = tid >> 5;
    const int lane = tid & 31;
    const int m0   = (bid * 8 + warp) * 16;
    if (m0 >= N) return;

    const int t = lane & 3, g = lane >> 2;
    const int r0 = m0 + g;
    const int r1 = m0 + g + 8;
    const bool r0ok = r0 < N;
    const bool r1ok = r1 < N;

    unsigned Ahi[8][4], Alo[8][4];
    const float* __restrict__ xr0 = X + (size_t)r0 * DD;
    const float* __restrict__ xr1 = X + (size_t)r1 * DD;
    #pragma unroll
    for (int k = 0; k < 8; k++) {
        float x0 = r0ok ? __ldg(&xr0[k * 8 + t])     : 0.f;
        float x1 = r1ok ? __ldg(&xr1[k * 8 + t])     : 0.f;
        float x2 = r0ok ? __ldg(&xr0[k * 8 + t + 4]) : 0.f;
        float x3 = r1ok ? __ldg(&xr1[k * 8 + t + 4]) : 0.f;
        Ahi[k][0] = f2tf32(x0); Alo[k][0] = f2tf32(x0 - __uint_as_float(Ahi[k][0]));
        Ahi[k][1] = f2tf32(x1); Alo[k][1] = f2tf32(x1 - __uint_as_float(Ahi[k][1]));
        Ahi[k][2] = f2tf32(x2); Alo[k][2] = f2tf32(x2 - __uint_as_float(Ahi[k][2]));
        Ahi[k][3] = f2tf32(x3); Alo[k][3] = f2tf32(x3 - __uint_as_float(Ahi[k][3]));
    }

    const uint2* __restrict__ sB2 = (const uint2*)sB;

    #pragma unroll
    for (int mat = 0; mat < 2; mat++) {
        #pragma unroll
        for (int n = 0; n < 8; n++) {
            float d0 = 0.f, d1 = 0.f, d2 = 0.f, d3 = 0.f;
            #pragma unroll
            for (int k = 0; k < 8; k++) {
                const int base = (((mat * 8 + n) * 8 + k) * 2) * 32 + lane;
                const uint2 bh = sB2[base];
                const uint2 bl = sB2[base + 32];
                MMA_TF32(d0, d1, d2, d3,
                         Ahi[k][0], Ahi[k][1], Ahi[k][2], Ahi[k][3], bh.x, bh.y);
                MMA_TF32(d0, d1, d2, d3,
                         Ahi[k][0], Ahi[k][1], Ahi[k][2], Ahi[k][3], bl.x, bl.y);
                MMA_TF32(d0, d1, d2, d3,
                         Alo[k][0], Alo[k][1], Alo[k][2], Alo[k][3], bh.x, bh.y);
            }
            const int c0 = n * 8 + 2 * t;      // even column
            const int li = c0 >> 2;
            const int offG = li * 8 + (c0 & 3);
            const int offP = li * 8 + 4 + (c0 & 3);
            if (mat == 0) {
                if (r0ok) *(__half2*)&g_EP[(size_t)r0 * 128 + offG] =
                    __floats2half2_rn(__expf(d0), __expf(d1));
                if (r1ok) *(__half2*)&g_EP[(size_t)r1 * 128 + offG] =
                    __floats2half2_rn(__expf(d2), __expf(d3));
            } else {
                const float b0v = __ldg(&Bm[c0]);
                const float b1v = __ldg(&Bm[c0 + 1]);
                if (r0ok) *(__half2*)&g_EP[(size_t)r0 * 128 + offP] =
                    __floats2half2_rn(fmaxf(d0 + b0v, 0.f), fmaxf(d1 + b1v, 0.f));
                if (r1ok) *(__half2*)&g_EP[(size_t)r1 * 128 + offP] =
                    __floats2half2_rn(fmaxf(d2 + b0v, 0.f), fmaxf(d3 + b1v, 0.f));
            }
        }
    }
}

// ---------------------------------------------------------------------------
// Scan, then scatter via saved ranks (no second atomic pass)
// ---------------------------------------------------------------------------
__global__ void __launch_bounds__(1024) scan1_kernel(int N)
{
    __shared__ int wsum[32];
    const int i    = blockIdx.x * 1024 + threadIdx.x;
    const int lane = threadIdx.x & 31;
    const int w    = threadIdx.x >> 5;

    int s = (i < N) ? g_cnt[i] : 0;
    #pragma unroll
    for (int d = 1; d < 32; d <<= 1) {
        int tv = __shfl_up_sync(0xffffffffu, s, d);
        if (lane >= d) s += tv;
    }
    if (lane == 31) wsum[w] = s;
    __syncthreads();
    if (w == 0) {
        int ws = wsum[lane];
        #pragma unroll
        for (int d = 1; d < 32; d <<= 1) {
            int tv = __shfl_up_sync(0xffffffffu, ws, d);
            if (lane >= d) ws += tv;
        }
        wsum[lane] = ws;
    }
    __syncthreads();
    if (w > 0) s += wsum[w - 1];
    if (i < N) g_incl[i] = s;
    if (threadIdx.x == 1023) g_btot[blockIdx.x] = s;
}

__global__ void __launch_bounds__(256) scan23_kernel(int N, int nblk)
{
    __shared__ int sm[128];
    if (threadIdx.x < 128)
        sm[threadIdx.x] = (threadIdx.x < nblk) ? g_btot[threadIdx.x] : 0;
    __syncthreads();
    #pragma unroll
    for (int d = 1; d < 128; d <<= 1) {
        int t = 0;
        if (threadIdx.x < 128 && threadIdx.x >= d) t = sm[threadIdx.x - d];
        __syncthreads();
        if (threadIdx.x < 128) sm[threadIdx.x] += t;
        __syncthreads();
    }
    const int i = blockIdx.x * blockDim.x + threadIdx.x;
    if (i < N) {
        const int blk = i >> 10;
        const int boff = (blk == 0) ? 0 : sm[blk - 1];
        g_start[i] = g_incl[i] - g_cnt[i] + boff;
    }
}

__global__ void __launch_bounds__(256) scatter_kernel(
    const int* __restrict__ rcv, int E)
{
    const int base = blockIdx.x * 1024;
    #pragma unroll
    for (int j = 0; j < 4; j++) {
        const int e = base + j * 256 + threadIdx.x;
        if (e < E) {
            const int pos = g_start[rcv[e]] + g_rank[e];
            g_edge[pos] = g_pay[e];
        }
    }
}

// ---------------------------------------------------------------------------
// Consume: one warp per receiver (grid-sized; HW scheduler backfill handles
// Poisson imbalance). Half-warps take contiguous halves of the edge range;
// 16 lanes cover D=64 (4 dims/lane). One LDG.128 per edge per lane, fp32
// accumulate, 4-edge unroll for MLP. Restores g_cnt=0 for the next call.
// ---------------------------------------------------------------------------
__device__ __forceinline__ void edge_accum(
    unsigned e, int li, const uint4* __restrict__ EP4,
    const float4* __restrict__ Eg4, float4& num, float4& den)
{
    const int s = (int)(e & 0x1FFFFu);
    const int t = (int)(e >> 17);

    const uint4  v  = EP4[s * 16 + li];        // expG x4 | P x4 (fp16)
    const float4 eg = Eg4[t * 16 + li];        // exp(Eg+Bg), fp32 (hot)

    const float2 g01 = __half22float2(*(const __half2*)&v.x);
    const float2 g23 = __half22float2(*(const __half2*)&v.y);
    const float2 p01 = __half22float2(*(const __half2*)&v.z);
    const float2 p23 = __half22float2(*(const __half2*)&v.w);

    const float ex0 = g01.x * eg.x;
    const float ex1 = g01.y * eg.y;
    const float ex2 = g23.x * eg.z;
    const float ex3 = g23.y * eg.w;

    den.x += ex0; den.y += ex1; den.z += ex2; den.w += ex3;
    num.x += p01.x * ex0;
    num.y += p01.y * ex1;
    num.z += p23.x * ex2;
    num.w += p23.y * ex3;
}

__global__ void __launch_bounds__(256) consume_kernel(float4* __restrict__ out, int N)
{
    const int gw = (blockIdx.x * blockDim.x + threadIdx.x) >> 5;  // receiver
    if (gw >= N) return;
    const int lane = threadIdx.x & 31;
    const int half = lane >> 4;
    const int li   = lane & 15;

    const int start = g_start[gw];
    const int cnt   = g_cnt[gw];
    const int mid   = start + ((cnt + 1) >> 1);
    const int lo    = half ? mid : start;
    const int hi    = half ? (start + cnt) : mid;

    const uint4*  EP4 = (const uint4*)g_EP;
    const float4* Eg4 = (const float4*)g_expEgb;

    float4 num = make_float4(0.f, 0.f, 0.f, 0.f);
    float4 den = make_float4(0.f, 0.f, 0.f, 0.f);

    int i = lo;
    for (; i + 3 < hi; i += 4) {
        const unsigned e0 = g_edge[i];
        const unsigned e1 = g_edge[i + 1];
        const unsigned e2 = g_edge[i + 2];
        const unsigned e3 = g_edge[i + 3];
        edge_accum(e0, li, EP4, Eg4, num, den);
        edge_accum(e1, li, EP4, Eg4, num, den);
        edge_accum(e2, li, EP4, Eg4, num, den);
        edge_accum(e3, li, EP4, Eg4, num, den);
    }
    for (; i < hi; i++) {
        edge_accum(g_edge[i], li, EP4, Eg4, num, den);
    }

    num.x += __shfl_xor_sync(0xffffffffu, num.x, 16);
    num.y += __shfl_xor_sync(0xffffffffu, num.y, 16);
    num.z += __shfl_xor_sync(0xffffffffu, num.z, 16);
    num.w += __shfl_xor_sync(0xffffffffu, num.w, 16);
    den.x += __shfl_xor_sync(0xffffffffu, den.x, 16);
    den.y += __shfl_xor_sync(0xffffffffu, den.y, 16);
    den.z += __shfl_xor_sync(0xffffffffu, den.z, 16);
    den.w += __shfl_xor_sync(0xffffffffu, den.w, 16);

    if (half == 0) {
        float4 v;
        v.x = (den.x > 0.f) ? num.x / den.x : 0.f;
        v.y = (den.y > 0.f) ? num.y / den.y : 0.f;
        v.z = (den.z > 0.f) ? num.z / den.z : 0.f;
        v.w = (den.w > 0.f) ? num.w / den.w : 0.f;
        out[gw * 16 + li] = v;
        if (li == 0) g_cnt[gw] = 0;   // restore invariant for next call
    }
}

extern "C" void kernel_launch(void* const* d_in, const int* in_sizes, int n_in,
                              void* d_out, int out_size)
{
    const float* node_codes = (const float*)d_in[0];
    const float* Vp         = (const float*)d_in[1];
    const float* Vg         = (const float*)d_in[2];
    const float* Eg         = (const float*)d_in[3];
    const float* Bm         = (const float*)d_in[4];
    const float* Bg         = (const float*)d_in[5];
    const int*   snd        = (const int*)d_in[6];
    const int*   rcv        = (const int*)d_in[7];
    const int*   typ        = (const int*)d_in[8];

    const int N = in_sizes[0] / DD;
    const int E = in_sizes[6];

    const int SMEM_B = 2 * 8 * 8 * 2 * 32 * 8;   // 65536 bytes
    cudaFuncSetAttribute(fused_front_kernel,
                         cudaFuncAttributeMaxDynamicSharedMemorySize, SMEM_B);

    {
        const int nodeBlocks = ((N + 15) / 16 + 7) / 8;
        const int egbBlocks  = (NREL * DD + 255) / 256;
        const int histBlocks = (E + 1023) / 1024;
        const int total = nodeBlocks + egbBlocks + histBlocks;
        fused_front_kernel<<<total, 256, SMEM_B>>>(
            node_codes, Vp, Vg, Bm, Eg, Bg, snd, rcv, typ,
            N, E, nodeBlocks, egbBlocks);
    }

    const int nblk = (N + 1023) / 1024;
    scan1_kernel<<<nblk, 1024>>>(N);
    scan23_kernel<<<(N + 255) / 256, 256>>>(N, nblk);

    scatter_kernel<<<(E + 1023) / 1024, 256>>>(rcv, E);

    {
        const long long threads = (long long)N * 32;
        const int blocks = (int)((threads + 255) / 256);
        consume_kernel<<<blocks, 256>>>((float4*)d_out, N);
    }
}